// round 6
// baseline (speedup 1.0000x reference)
#include <cuda_runtime.h>
#include <cuda_bf16.h>

#define NN 100000
#define EE 1600000
#define NSEG (NN * 8)
#define NPB 32
#define NTILES (NN / NPB)        // 3125
#define GRID 148
#define AST 584                  // A row stride (bf16)
#define WST 1160                 // W smem row stride (bf16): 1152 + 8
#define KW 1152                  // packed W row: [0,576)=hi, [576,1152)=lo
#define SMEM_P ((2 * NPB * AST + 64 * WST) * 2)   // 223232 B

__device__ __align__(16) unsigned g_cnt[NSEG];
__device__ __align__(16) unsigned g_off[NSEG + 1];
__device__ __align__(16) unsigned g_woff[NSEG];
__device__ __align__(16) unsigned g_bsum[512];
__device__ __align__(16) int      g_sb[EE];
__device__ __align__(16) int      g_ssrc[EE];    // src | rel<<20
__device__ __align__(16) float    g_h[(size_t)NN * 64];
__device__ __align__(16) float    g_h2[(size_t)NN * 64];
__device__ __align__(16) float    g_acc[128];
__device__ __align__(16) float    g_scale[64];
__device__ __align__(16) float    g_shift[64];
__device__ __align__(16) __nv_bfloat16 g_wp1[64 * KW];
__device__ __align__(16) __nv_bfloat16 g_wp2[64 * KW];

__global__ void zero_kernel(unsigned* cnt, float* acc) {
    int i = blockIdx.x * 256 + threadIdx.x;
    if (i < NSEG) cnt[i] = 0u;
    if (i < 128) acc[i] = 0.f;
}

__global__ void hist_kernel(const int* __restrict__ ei, const int* __restrict__ et,
                            int* __restrict__ sb, unsigned* __restrict__ cnt) {
    int e = blockIdx.x * 256 + threadIdx.x;
    if (e >= EE) return;
    int b = ei[EE + e] * 8 + et[e];
    sb[e] = b;
    atomicAdd(cnt + b, 1u);
}

__global__ void scan1(const unsigned* __restrict__ cnt, unsigned* __restrict__ off,
                      unsigned* __restrict__ bsum) {
    __shared__ unsigned sh[256];
    int t = threadIdx.x;
    int base = blockIdx.x * 2048 + t * 8;
    unsigned v[8], s = 0;
#pragma unroll
    for (int j = 0; j < 8; j++) { v[j] = (base + j < NSEG) ? cnt[base + j] : 0u; s += v[j]; }
    sh[t] = s; __syncthreads();
    for (int d = 1; d < 256; d <<= 1) {
        unsigned x = (t >= d) ? sh[t - d] : 0u;
        __syncthreads(); sh[t] += x; __syncthreads();
    }
    if (t == 255) bsum[blockIdx.x] = sh[255];
    unsigned run = sh[t] - s;
#pragma unroll
    for (int j = 0; j < 8; j++)
        if (base + j < NSEG) { off[base + j] = run; run += v[j]; }
}

__global__ void scan2(unsigned* bsum, int nb) {
    __shared__ unsigned sh[512];
    int t = threadIdx.x;
    unsigned v = (t < nb) ? bsum[t] : 0u;
    sh[t] = v; __syncthreads();
    for (int d = 1; d < 512; d <<= 1) {
        unsigned x = (t >= d) ? sh[t - d] : 0u;
        __syncthreads(); sh[t] += x; __syncthreads();
    }
    if (t < nb) bsum[t] = sh[t] - v;
}

__global__ void scan3(unsigned* __restrict__ off, unsigned* __restrict__ woff,
                      const unsigned* __restrict__ bsum) {
    int i = blockIdx.x * 256 + threadIdx.x;
    if (i < NSEG) { unsigned o = off[i] + bsum[i >> 11]; off[i] = o; woff[i] = o; }
    if (i == 0) off[NSEG] = EE;
}

__global__ void sort_kernel(const int* __restrict__ ei, const int* __restrict__ sb,
                            unsigned* __restrict__ woff, int* __restrict__ ssrc) {
    int e = blockIdx.x * 256 + threadIdx.x;
    if (e >= EE) return;
    int b = sb[e];
    unsigned pos = atomicAdd(woff + b, 1u);
    ssrc[pos] = ei[e] | ((b & 7) << 20);
}

__global__ void prep_w(const float* __restrict__ w, const float* __restrict__ root,
                       __nv_bfloat16* __restrict__ wp) {
    int i = blockIdx.x * 256 + threadIdx.x;
    if (i >= 64 * KW) return;
    int j = i / KW, k = i % KW;
    int kk = (k < 576) ? k : k - 576;
    float v = (kk < 512) ? w[((size_t)(kk >> 6) * 64 + (kk & 63)) * 64 + j]
                         : root[(size_t)(kk - 512) * 64 + j];
    __nv_bfloat16 hi = __float2bfloat16(v);
    wp[i] = (k < 576) ? hi : __float2bfloat16(v - __bfloat162float(hi));
}

__device__ __forceinline__ void cp16(void* dst, const void* src) {
    unsigned s = (unsigned)__cvta_generic_to_shared(dst);
    asm volatile("cp.async.cg.shared.global [%0], [%1], 16;" :: "r"(s), "l"(src));
}

#define MMA16816(c0,c1,c2,c3,a0,a1,a2,a3,b0,b1)                                     \
    asm volatile("mma.sync.aligned.m16n8k16.row.col.f32.bf16.bf16.f32 "             \
                 "{%0,%1,%2,%3},{%4,%5,%6,%7},{%8,%9},{%0,%1,%2,%3};"               \
                 : "+f"(c0), "+f"(c1), "+f"(c2), "+f"(c3)                           \
                 : "r"(a0), "r"(a1), "r"(a2), "r"(a3), "r"(b0), "r"(b1))

__device__ __forceinline__ void store_hilo(__nv_bfloat16* Ah, __nv_bfloat16* Al,
                                           int row, int col2, float ax, float ay, int lane) {
    __nv_bfloat162 h, l;
    h.x = __float2bfloat16(ax); h.y = __float2bfloat16(ay);
    l.x = __float2bfloat16(ax - __bfloat162float(h.x));
    l.y = __float2bfloat16(ay - __bfloat162float(h.y));
    ((__nv_bfloat162*)(Ah + row * AST + col2))[lane] = h;
    ((__nv_bfloat162*)(Al + row * AST + col2))[lane] = l;
}

__global__ void __launch_bounds__(1024, 1)
fused_kernel(const float* __restrict__ X, const __nv_bfloat16* __restrict__ WP,
             const float* __restrict__ bias, const unsigned* __restrict__ off,
             const int* __restrict__ ssrc, float* __restrict__ OUT) {
    extern __shared__ char smem[];
    __nv_bfloat16* Ah = (__nv_bfloat16*)smem;           // [32][AST]
    __nv_bfloat16* Al = Ah + NPB * AST;
    __nv_bfloat16* Ws = Al + NPB * AST;                 // [64][WST]
    float* P = (float*)smem;                            // k-split partials (dead A)

    const int tid = threadIdx.x, wid = tid >> 5, lane = tid & 31;
    const int g = lane >> 2, tig = lane & 3;
    const int tile = wid & 3, ks = wid >> 2;
    const int mt = tile & 1, ntl = tile >> 1;

    // resident W load (once per block)
    for (int i = tid; i < 64 * 144; i += 1024) {
        int j = i / 144, sg = i % 144;
        cp16(Ws + j * WST + sg * 8, WP + (size_t)j * KW + sg * 8);
    }
    asm volatile("cp.async.commit_group;");
    asm volatile("cp.async.wait_group 0;");

    for (int t = blockIdx.x; t < NTILES; t += GRID) {
        const int nb = t * NPB;

        // root region: A cols [512,576) = X rows (1 float2/thread)
        {
            float2 v = *(const float2*)(X + (size_t)(nb + wid) * 64 + lane * 2);
            store_hilo(Ah, Al, wid, 512, v.x, v.y, lane);
        }

        // gather: warp <-> node, rel-sorted edge walk with flush-on-change
        {
            const unsigned* offp = off + (size_t)(nb + wid) * 8u;
            unsigned e0 = offp[0];
            int cnt = (int)(offp[8] - e0);
            int pk[4];
#pragma unroll
            for (int j = 0; j < 4; j++) pk[j] = (j < cnt) ? ssrc[e0 + j] : -1;
            float ax = 0.f, ay = 0.f;
            int curr = -1;
            unsigned done = 0;
            for (int base = 0; base < cnt; base += 4) {
                int nk[4];
#pragma unroll
                for (int j = 0; j < 4; j++)
                    nk[j] = (base + 4 + j < cnt) ? ssrc[e0 + base + 4 + j] : -1;
                float2 v[4];
#pragma unroll
                for (int j = 0; j < 4; j++) {
                    v[j] = make_float2(0.f, 0.f);
                    if (pk[j] >= 0)
                        v[j] = *(const float2*)(X + (size_t)(pk[j] & 0xFFFFF) * 64 + lane * 2);
                }
#pragma unroll
                for (int j = 0; j < 4; j++) {
                    if (pk[j] >= 0) {
                        int r = pk[j] >> 20;
                        if (r != curr) {
                            if (curr >= 0) {
                                float inv = 1.f / (float)(offp[curr + 1] - offp[curr]);
                                store_hilo(Ah, Al, wid, curr * 64, ax * inv, ay * inv, lane);
                            }
                            curr = r; ax = 0.f; ay = 0.f; done |= 1u << r;
                        }
                        ax += v[j].x; ay += v[j].y;
                    }
                }
#pragma unroll
                for (int j = 0; j < 4; j++) pk[j] = nk[j];
            }
            if (curr >= 0) {
                float inv = 1.f / (float)(offp[curr + 1] - offp[curr]);
                store_hilo(Ah, Al, wid, curr * 64, ax * inv, ay * inv, lane);
            }
#pragma unroll
            for (int r = 0; r < 8; r++)
                if (!((done >> r) & 1)) store_hilo(Ah, Al, wid, r * 64, 0.f, 0.f, lane);
        }
        __syncthreads();

        // GEMM: warp tile m16n32, 8-way k-split over 108 ktiles (3 terms x 36)
        float c_[4][4];
#pragma unroll
        for (int nt = 0; nt < 4; nt++)
#pragma unroll
            for (int k = 0; k < 4; k++) c_[nt][k] = 0.f;

        for (int idx = ks; idx < 108; idx += 8) {
            int term = idx / 36;
            int k = (idx - term * 36) * 16;
            const __nv_bfloat16* ap = ((term == 1) ? Al : Ah)
                                      + (mt * 16 + g) * AST + k + 2 * tig;
            unsigned a0 = *(const unsigned*)(ap);
            unsigned a2 = *(const unsigned*)(ap + 8);
            unsigned a1 = *(const unsigned*)(ap + 8 * AST);
            unsigned a3 = *(const unsigned*)(ap + 8 * AST + 8);
            int koff = ((term == 2) ? 576 : 0) + k + 2 * tig;
#pragma unroll
            for (int nt = 0; nt < 4; nt++) {
                const __nv_bfloat16* bp = Ws + (ntl * 32 + nt * 8 + g) * WST + koff;
                unsigned b0 = *(const unsigned*)(bp);
                unsigned b1 = *(const unsigned*)(bp + 8);
                MMA16816(c_[nt][0], c_[nt][1], c_[nt][2], c_[nt][3],
                         a0, a1, a2, a3, b0, b1);
            }
        }
        __syncthreads();

        // k-split partials -> smem (slots of 16x33 floats), warps ks>0 only
        if (ks > 0) {
            float* dst = P + wid * (16 * 33);
#pragma unroll
            for (int nt = 0; nt < 4; nt++)
#pragma unroll
                for (int k = 0; k < 4; k++)
                    dst[((k >> 1) * 8 + g) * 33 + nt * 8 + 2 * tig + (k & 1)] = c_[nt][k];
        }
        __syncthreads();

        // reduce + store (4 warps, ks==0: wid==tile)
        if (wid < 4) {
#pragma unroll 1
            for (int w = 1; w < 8; w++) {
                const float* src = P + (w * 4 + wid) * (16 * 33);
#pragma unroll
                for (int nt = 0; nt < 4; nt++)
#pragma unroll
                    for (int k = 0; k < 4; k++)
                        c_[nt][k] += src[((k >> 1) * 8 + g) * 33 + nt * 8 + 2 * tig + (k & 1)];
            }
            int row0 = nb + mt * 16 + g;
#pragma unroll
            for (int nt = 0; nt < 4; nt++) {
                int col = ntl * 32 + nt * 8 + 2 * tig;
                float2 bb = *(const float2*)(bias + col);
                *(float2*)(OUT + (size_t)row0 * 64 + col)
                    = make_float2(c_[nt][0] + bb.x, c_[nt][1] + bb.y);
                *(float2*)(OUT + (size_t)(row0 + 8) * 64 + col)
                    = make_float2(c_[nt][2] + bb.x, c_[nt][3] + bb.y);
            }
        }
        __syncthreads();
    }
}

__global__ void bn_stats(const float* __restrict__ H, float* __restrict__ acc) {
    int ch = threadIdx.x & 63, ry = threadIdx.x >> 6;
    float s = 0.f, q = 0.f;
    for (int r = blockIdx.x * 4 + ry; r < NN; r += gridDim.x * 4) {
        float v = H[(size_t)r * 64 + ch];
        s += v; q += v * v;
    }
    __shared__ float sh[2][4][64];
    sh[0][ry][ch] = s; sh[1][ry][ch] = q;
    __syncthreads();
    if (ry == 0) {
        s = sh[0][0][ch] + sh[0][1][ch] + sh[0][2][ch] + sh[0][3][ch];
        q = sh[1][0][ch] + sh[1][1][ch] + sh[1][2][ch] + sh[1][3][ch];
        atomicAdd(acc + ch, s);
        atomicAdd(acc + 64 + ch, q);
    }
}

__global__ void bn_final(const float* __restrict__ acc, const float* __restrict__ gamma,
                         const float* __restrict__ beta, float* __restrict__ scale,
                         float* __restrict__ shift) {
    int ch = threadIdx.x;
    if (ch >= 64) return;
    const float invN = 1.0f / (float)NN;
    float mu = acc[ch] * invN;
    float var = acc[64 + ch] * invN - mu * mu;
    float sc = gamma[ch] * rsqrtf(var + 1e-5f);
    scale[ch] = sc;
    shift[ch] = beta[ch] - mu * sc;
}

__global__ void bn_apply(const float* __restrict__ H, const float* __restrict__ scale,
                         const float* __restrict__ shift, float* __restrict__ H2) {
    int i = blockIdx.x * 512 + threadIdx.x;
    if (i >= NN * 64) return;
    int ch = i & 63;
    H2[i] = fmaxf(H[i] * scale[ch] + shift[ch], 0.f);
}

extern "C" void kernel_launch(void* const* d_in, const int* in_sizes, int n_in,
                              void* d_out, int out_size) {
    const float* x      = (const float*)d_in[0];
    const int*   ei     = (const int*)d_in[1];
    const int*   etype  = (const int*)d_in[2];
    const float* w1     = (const float*)d_in[3];
    const float* root1  = (const float*)d_in[4];
    const float* b1     = (const float*)d_in[5];
    const float* gamma1 = (const float*)d_in[6];
    const float* beta1  = (const float*)d_in[7];
    const float* w2     = (const float*)d_in[8];
    const float* root2  = (const float*)d_in[9];
    const float* b2     = (const float*)d_in[10];
    float* out = (float*)d_out;

    unsigned *cnt, *off, *woff, *bsum;
    int *sb, *ssrc;
    float *h, *h2, *acc, *scale, *shift;
    __nv_bfloat16 *wp1, *wp2;
    cudaGetSymbolAddress((void**)&cnt, g_cnt);
    cudaGetSymbolAddress((void**)&off, g_off);
    cudaGetSymbolAddress((void**)&woff, g_woff);
    cudaGetSymbolAddress((void**)&bsum, g_bsum);
    cudaGetSymbolAddress((void**)&sb, g_sb);
    cudaGetSymbolAddress((void**)&ssrc, g_ssrc);
    cudaGetSymbolAddress((void**)&h, g_h);
    cudaGetSymbolAddress((void**)&h2, g_h2);
    cudaGetSymbolAddress((void**)&acc, g_acc);
    cudaGetSymbolAddress((void**)&scale, g_scale);
    cudaGetSymbolAddress((void**)&shift, g_shift);
    cudaGetSymbolAddress((void**)&wp1, g_wp1);
    cudaGetSymbolAddress((void**)&wp2, g_wp2);

    cudaFuncSetAttribute(fused_kernel, cudaFuncAttributeMaxDynamicSharedMemorySize, SMEM_P);

    const int NB_SCAN1 = (NSEG + 2047) / 2048;

    zero_kernel<<<(NSEG + 255) / 256, 256>>>(cnt, acc);
    hist_kernel<<<(EE + 255) / 256, 256>>>(ei, etype, sb, cnt);
    scan1<<<NB_SCAN1, 256>>>(cnt, off, bsum);
    scan2<<<1, 512>>>(bsum, NB_SCAN1);
    scan3<<<(NSEG + 255) / 256, 256>>>(off, woff, bsum);
    sort_kernel<<<(EE + 255) / 256, 256>>>(ei, sb, woff, ssrc);
    prep_w<<<(64 * KW + 255) / 256, 256>>>(w1, root1, wp1);
    prep_w<<<(64 * KW + 255) / 256, 256>>>(w2, root2, wp2);

    fused_kernel<<<GRID, 1024, SMEM_P>>>(x, wp1, b1, off, ssrc, h);

    bn_stats<<<1024, 256>>>(h, acc);
    bn_final<<<1, 64>>>(acc, gamma1, beta1, scale, shift);
    bn_apply<<<(NN * 64 + 511) / 512, 512>>>(h, scale, shift, h2);

    fused_kernel<<<GRID, 1024, SMEM_P>>>(h2, wp2, b2, off, ssrc, out);
}

// round 7
// speedup vs baseline: 1.0440x; 1.0440x over previous
#include <cuda_runtime.h>
#include <cuda_bf16.h>

#define NN 100000
#define EE 1600000
#define NDSEG (NN * 8)          // (dst,rel) bins for mean counts
#define KDIM 192                // bf16 split K: [hi | lo | hi]
#define ASTRIDE 200
#define SMEM_BYTES (128*ASTRIDE*2 + 2*64*ASTRIDE*2)

// ---------------- device scratch ----------------
__device__ __align__(16) float    g_y[(size_t)NN * 512];
__device__ __align__(16) float    g_h[(size_t)NN * 64];
__device__ __align__(16) unsigned g_cntd[NDSEG];      // counts per (dst*8+rel)
__device__ __align__(16) unsigned g_cnts[NN];         // counts per src
__device__ __align__(16) unsigned g_off[NN + 1];      // src offsets
__device__ __align__(16) unsigned g_woff[NN];
__device__ __align__(16) unsigned g_bsum[512];
__device__ __align__(16) int      g_sa[EE];           // sorted: src*8+et
__device__ __align__(16) int      g_sd[EE];           // sorted: dst*8+et
__device__ __align__(16) float    g_acc[128];
__device__ __align__(16) float    g_scale[64];
__device__ __align__(16) float    g_shift[64];
__device__ __align__(16) __nv_bfloat16 g_wp1[576 * KDIM];
__device__ __align__(16) __nv_bfloat16 g_wp2[576 * KDIM];

// ---------------- prep ----------------
__global__ void hist_kernel(const int* __restrict__ ei, const int* __restrict__ et,
                            unsigned* __restrict__ cnts, unsigned* __restrict__ cntd) {
    int e = blockIdx.x * 256 + threadIdx.x;
    if (e >= EE) return;
    atomicAdd(cnts + ei[e], 1u);
    atomicAdd(cntd + ei[EE + e] * 8 + et[e], 1u);
}

__global__ void scan1(const unsigned* __restrict__ cnt, unsigned* __restrict__ off,
                      unsigned* __restrict__ bsum) {
    __shared__ unsigned sh[256];
    int t = threadIdx.x;
    int base = blockIdx.x * 2048 + t * 8;
    unsigned v[8], s = 0;
#pragma unroll
    for (int j = 0; j < 8; j++) { v[j] = (base + j < NN) ? cnt[base + j] : 0u; s += v[j]; }
    sh[t] = s; __syncthreads();
    for (int d = 1; d < 256; d <<= 1) {
        unsigned x = (t >= d) ? sh[t - d] : 0u;
        __syncthreads(); sh[t] += x; __syncthreads();
    }
    if (t == 255) bsum[blockIdx.x] = sh[255];
    unsigned run = sh[t] - s;
#pragma unroll
    for (int j = 0; j < 8; j++)
        if (base + j < NN) { off[base + j] = run; run += v[j]; }
}

__global__ void scan2(unsigned* bsum, int nb) {
    __shared__ unsigned sh[512];
    int t = threadIdx.x;
    unsigned v = (t < nb) ? bsum[t] : 0u;
    sh[t] = v; __syncthreads();
    for (int d = 1; d < 512; d <<= 1) {
        unsigned x = (t >= d) ? sh[t - d] : 0u;
        __syncthreads(); sh[t] += x; __syncthreads();
    }
    if (t < nb) bsum[t] = sh[t] - v;
}

__global__ void scan3(unsigned* __restrict__ off, unsigned* __restrict__ woff,
                      const unsigned* __restrict__ bsum) {
    int i = blockIdx.x * 256 + threadIdx.x;
    if (i < NN) { unsigned o = off[i] + bsum[i >> 11]; off[i] = o; woff[i] = o; }
    if (i == 0) off[NN] = EE;
}

__global__ void sort_kernel(const int* __restrict__ ei, const int* __restrict__ et,
                            unsigned* __restrict__ woff,
                            int* __restrict__ sa, int* __restrict__ sd) {
    int e = blockIdx.x * 256 + threadIdx.x;
    if (e >= EE) return;
    int s = ei[e], d = ei[EE + e], r = et[e];
    unsigned pos = atomicAdd(woff + s, 1u);
    sa[pos] = s * 8 + r;
    sd[pos] = d * 8 + r;
}

// pack W[r,d,o] (+root as r==8) -> [j=r*64+o][k], k<128: hi (d=k%64), else lo
__global__ void prep_w(const float* __restrict__ w, const float* __restrict__ root,
                       __nv_bfloat16* __restrict__ wp) {
    int i = blockIdx.x * 256 + threadIdx.x;
    if (i >= 576 * KDIM) return;
    int j = i / KDIM, k = i % KDIM;
    int r = j >> 6, o = j & 63;
    int d = (k < 64) ? k : (k < 128 ? k - 64 : k - 128);
    float v = (r < 8) ? w[((size_t)r * 64 + d) * 64 + o] : root[(size_t)d * 64 + o];
    __nv_bfloat16 hi = __float2bfloat16(v);
    wp[i] = (k < 128) ? hi : __float2bfloat16(v - __bfloat162float(hi));
}

// ---------------- GEMM (same as R2 best) ----------------
__device__ __forceinline__ void cp16(void* dst, const void* src) {
    unsigned s = (unsigned)__cvta_generic_to_shared(dst);
    asm volatile("cp.async.cg.shared.global [%0], [%1], 16;" :: "r"(s), "l"(src));
}

__device__ __forceinline__ void issue_b_chunk(__nv_bfloat16* bbuf,
                                              const __nv_bfloat16* wp, int nc, int tid) {
    const __nv_bfloat16* src0 = wp + (size_t)nc * 64 * KDIM;
#pragma unroll
    for (int i = 0; i < 6; i++) {
        int t = tid + i * 256;
        int j = t / 24, seg = t % 24;
        cp16(bbuf + j * ASTRIDE + seg * 8, src0 + j * KDIM + seg * 8);
    }
}

#define MMA16816(c0,c1,c2,c3,a0,a1,a2,a3,b0,b1)                                     \
    asm volatile("mma.sync.aligned.m16n8k16.row.col.f32.bf16.bf16.f32 "             \
                 "{%0,%1,%2,%3},{%4,%5,%6,%7},{%8,%9},{%0,%1,%2,%3};"               \
                 : "+f"(c0), "+f"(c1), "+f"(c2), "+f"(c3)                           \
                 : "r"(a0), "r"(a1), "r"(a2), "r"(a3), "r"(b0), "r"(b1))

template <bool APPLY_BN>
__global__ void __launch_bounds__(256, 2)
gemm_kernel(const float* __restrict__ X, const __nv_bfloat16* __restrict__ WP,
            const float* __restrict__ bias,
            const float* __restrict__ bnscale, const float* __restrict__ bnshift,
            float* __restrict__ Y, float* __restrict__ OUT) {
    extern __shared__ char smem[];
    __nv_bfloat16* As = (__nv_bfloat16*)smem;
    __nv_bfloat16* Bs = (__nv_bfloat16*)(smem + 128 * ASTRIDE * 2);

    const int tid = threadIdx.x;
    const int wid = tid >> 5, lane = tid & 31;
    const int g = lane >> 2, tig = lane & 3;
    const int warpM = wid & 3, warpN = wid >> 2;
    const int mbase = blockIdx.x * 128;

    for (int it = tid; it < 128 * 32; it += 256) {
        int row = it >> 5, dp = it & 31;
        int grow = mbase + row;
        float2 v = make_float2(0.f, 0.f);
        if (grow < NN) v = *(const float2*)(X + (size_t)grow * 64 + dp * 2);
        if (APPLY_BN) {
            v.x = fmaxf(v.x * bnscale[dp * 2]     + bnshift[dp * 2], 0.f);
            v.y = fmaxf(v.y * bnscale[dp * 2 + 1] + bnshift[dp * 2 + 1], 0.f);
        }
        __nv_bfloat162 hi, lo;
        hi.x = __float2bfloat16(v.x); hi.y = __float2bfloat16(v.y);
        lo.x = __float2bfloat16(v.x - __bfloat162float(hi.x));
        lo.y = __float2bfloat16(v.y - __bfloat162float(hi.y));
        __nv_bfloat162* arow = (__nv_bfloat162*)(As + row * ASTRIDE);
        arow[dp] = hi; arow[32 + dp] = lo; arow[64 + dp] = hi;
    }

    issue_b_chunk(Bs, WP, 0, tid);
    asm volatile("cp.async.commit_group;");

    float c[2][4][4];
#pragma unroll
    for (int a = 0; a < 2; a++)
#pragma unroll
        for (int b = 0; b < 4; b++)
#pragma unroll
            for (int k = 0; k < 4; k++) c[a][b][k] = 0.f;

    const __nv_bfloat16* a0p = As + (warpM * 32 + g) * ASTRIDE;

    for (int nc = 0; nc < 9; nc++) {
        if (nc + 1 < 9) {
            issue_b_chunk(Bs + ((nc + 1) & 1) * 64 * ASTRIDE, WP, nc + 1, tid);
            asm volatile("cp.async.commit_group;");
            asm volatile("cp.async.wait_group 1;");
        } else {
            asm volatile("cp.async.wait_group 0;");
        }
        __syncthreads();

        const __nv_bfloat16* Bb = Bs + (nc & 1) * 64 * ASTRIDE + (warpN * 32 + g) * ASTRIDE;
#pragma unroll
        for (int ks = 0; ks < 12; ks++) {
            const int kc = ks * 16 + 2 * tig;
            unsigned a[2][4], b[4][2];
#pragma unroll
            for (int mt = 0; mt < 2; mt++) {
                const __nv_bfloat16* ap = a0p + mt * 16 * ASTRIDE + kc;
                a[mt][0] = *(const unsigned*)(ap);
                a[mt][2] = *(const unsigned*)(ap + 8);
                a[mt][1] = *(const unsigned*)(ap + 8 * ASTRIDE);
                a[mt][3] = *(const unsigned*)(ap + 8 * ASTRIDE + 8);
            }
#pragma unroll
            for (int nt = 0; nt < 4; nt++) {
                const __nv_bfloat16* bp = Bb + nt * 8 * ASTRIDE + kc;
                b[nt][0] = *(const unsigned*)(bp);
                b[nt][1] = *(const unsigned*)(bp + 8);
            }
#pragma unroll
            for (int mt = 0; mt < 2; mt++)
#pragma unroll
                for (int nt = 0; nt < 4; nt++)
                    MMA16816(c[mt][nt][0], c[mt][nt][1], c[mt][nt][2], c[mt][nt][3],
                             a[mt][0], a[mt][1], a[mt][2], a[mt][3], b[nt][0], b[nt][1]);
        }
        __syncthreads();

#pragma unroll
        for (int mt = 0; mt < 2; mt++)
#pragma unroll
            for (int nt = 0; nt < 4; nt++) {
                float* cc = c[mt][nt];
                int row = mbase + warpM * 32 + mt * 16 + g;
                int col = warpN * 32 + nt * 8 + 2 * tig;
                if (nc < 8) {
                    size_t base = (size_t)row * 512 + nc * 64 + col;
                    if (row < NN)     *(float2*)(Y + base)           = make_float2(cc[0], cc[1]);
                    if (row + 8 < NN) *(float2*)(Y + base + 8 * 512) = make_float2(cc[2], cc[3]);
                } else {
                    float2 bb = *(const float2*)(bias + col);
                    if (row < NN)
                        *(float2*)(OUT + (size_t)row * 64 + col) = make_float2(cc[0] + bb.x, cc[1] + bb.y);
                    if (row + 8 < NN)
                        *(float2*)(OUT + (size_t)(row + 8) * 64 + col) = make_float2(cc[2] + bb.x, cc[3] + bb.y);
                }
                cc[0] = cc[1] = cc[2] = cc[3] = 0.f;
            }
    }
}

// ---------------- scatter (src-sorted: sequential Y reads, L2 atomics out) ----------------
__global__ void scatter_kernel(const float* __restrict__ Y,
                               const int* __restrict__ SA, const int* __restrict__ SD,
                               const unsigned* __restrict__ CNTD, float* __restrict__ OUT) {
    int idx = blockIdx.x * 256 + threadIdx.x;
    int e = idx >> 4;
    if (e >= EE) return;
    int q = idx & 15;
    int sa = __ldg(SA + e), sd = __ldg(SD + e);
    float inv = 1.0f / fmaxf((float)__ldg(CNTD + sd), 1.0f);
    float4 v = *(const float4*)(Y + (size_t)sa * 64 + q * 4);
    float* dst = OUT + (size_t)(sd >> 3) * 64 + q * 4;
    asm volatile("red.global.add.v4.f32 [%0], {%1,%2,%3,%4};"
                 :: "l"(dst), "f"(v.x * inv), "f"(v.y * inv), "f"(v.z * inv), "f"(v.w * inv)
                 : "memory");
}

// ---------------- batch norm ----------------
__global__ void bn_stats(const float* __restrict__ H, float* __restrict__ acc) {
    int ch = threadIdx.x & 63, ry = threadIdx.x >> 6;
    float s = 0.f, q = 0.f;
    for (int r = blockIdx.x * 4 + ry; r < NN; r += gridDim.x * 4) {
        float v = H[(size_t)r * 64 + ch];
        s += v; q += v * v;
    }
    __shared__ float sh[2][4][64];
    sh[0][ry][ch] = s; sh[1][ry][ch] = q;
    __syncthreads();
    if (ry == 0) {
        s = sh[0][0][ch] + sh[0][1][ch] + sh[0][2][ch] + sh[0][3][ch];
        q = sh[1][0][ch] + sh[1][1][ch] + sh[1][2][ch] + sh[1][3][ch];
        atomicAdd(acc + ch, s);
        atomicAdd(acc + 64 + ch, q);
    }
}

__global__ void bn_final(const float* __restrict__ acc, const float* __restrict__ gamma,
                         const float* __restrict__ beta,
                         float* __restrict__ scale, float* __restrict__ shift) {
    int ch = threadIdx.x;
    if (ch >= 64) return;
    const float invN = 1.0f / (float)NN;
    float mu = acc[ch] * invN;
    float var = acc[64 + ch] * invN - mu * mu;
    float sc = gamma[ch] * rsqrtf(var + 1e-5f);
    scale[ch] = sc;
    shift[ch] = beta[ch] - mu * sc;
}

// ---------------- launcher ----------------
extern "C" void kernel_launch(void* const* d_in, const int* in_sizes, int n_in,
                              void* d_out, int out_size) {
    const float* x      = (const float*)d_in[0];
    const int*   ei     = (const int*)d_in[1];
    const int*   etype  = (const int*)d_in[2];
    const float* w1     = (const float*)d_in[3];
    const float* root1  = (const float*)d_in[4];
    const float* b1     = (const float*)d_in[5];
    const float* gamma1 = (const float*)d_in[6];
    const float* beta1  = (const float*)d_in[7];
    const float* w2     = (const float*)d_in[8];
    const float* root2  = (const float*)d_in[9];
    const float* b2     = (const float*)d_in[10];
    float* out = (float*)d_out;

    float *y, *h, *acc, *scale, *shift;
    unsigned *cntd, *cnts, *off, *woff, *bsum;
    int *sa, *sd;
    __nv_bfloat16 *wp1, *wp2;
    cudaGetSymbolAddress((void**)&y, g_y);
    cudaGetSymbolAddress((void**)&h, g_h);
    cudaGetSymbolAddress((void**)&cntd, g_cntd);
    cudaGetSymbolAddress((void**)&cnts, g_cnts);
    cudaGetSymbolAddress((void**)&off, g_off);
    cudaGetSymbolAddress((void**)&woff, g_woff);
    cudaGetSymbolAddress((void**)&bsum, g_bsum);
    cudaGetSymbolAddress((void**)&sa, g_sa);
    cudaGetSymbolAddress((void**)&sd, g_sd);
    cudaGetSymbolAddress((void**)&acc, g_acc);
    cudaGetSymbolAddress((void**)&scale, g_scale);
    cudaGetSymbolAddress((void**)&shift, g_shift);
    cudaGetSymbolAddress((void**)&wp1, g_wp1);
    cudaGetSymbolAddress((void**)&wp2, g_wp2);

    cudaFuncSetAttribute(gemm_kernel<false>, cudaFuncAttributeMaxDynamicSharedMemorySize, SMEM_BYTES);
    cudaFuncSetAttribute(gemm_kernel<true>,  cudaFuncAttributeMaxDynamicSharedMemorySize, SMEM_BYTES);

    const int MT = (NN + 127) / 128;             // 782
    const int SCGRID = (EE * 16) / 256;          // 100000
    const int NB1 = (NN + 2047) / 2048;          // 49

    // zero via memsets (graph-capturable, not kernel launches)
    cudaMemsetAsync(cnts, 0, NN * sizeof(unsigned), 0);
    cudaMemsetAsync(cntd, 0, NDSEG * sizeof(unsigned), 0);
    cudaMemsetAsync(acc, 0, 128 * sizeof(float), 0);

    // launch #1..#3
    prep_w<<<(576 * KDIM + 255) / 256, 256>>>(w1, root1, wp1);
    prep_w<<<(576 * KDIM + 255) / 256, 256>>>(w2, root2, wp2);
    hist_kernel<<<(EE + 255) / 256, 256>>>(ei, etype, cnts, cntd);
    // launch #4 (ncu-profiled slot): layer-1 GEMM
    gemm_kernel<false><<<MT, 256, SMEM_BYTES>>>(x, wp1, b1, nullptr, nullptr, y, h);
    // sort pipeline
    scan1<<<NB1, 256>>>(cnts, off, bsum);
    scan2<<<1, 512>>>(bsum, NB1);
    scan3<<<(NN + 255) / 256, 256>>>(off, woff, bsum);
    sort_kernel<<<(EE + 255) / 256, 256>>>(ei, etype, woff, sa, sd);
    // layer-1 scatter into h
    scatter_kernel<<<SCGRID, 256>>>(y, sa, sd, cntd, h);
    // BN (folded into gemm2 A-load)
    bn_stats<<<1024, 256>>>(h, acc);
    bn_final<<<1, 64>>>(acc, gamma1, beta1, scale, shift);
    // layer 2
    gemm_kernel<true><<<MT, 256, SMEM_BYTES>>>(h, wp2, b2, scale, shift, y, out);
    scatter_kernel<<<SCGRID, 256>>>(y, sa, sd, cntd, out);
}

// round 8
// speedup vs baseline: 1.2158x; 1.1645x over previous
#include <cuda_runtime.h>
#include <cuda_bf16.h>

#define NN 100000
#define EE 1600000
#define NSEG (NN * 8)
#define AST 136                 // A smem row stride (bf16): [Ah 64 | Al 64 | pad 8]
#define BST 136                 // B smem row stride (bf16): [Bh 64 | Bl 64 | pad 8]
#define KW 128                  // packed W row: [0,64)=hi, [64,128)=lo
#define SMEM_BYTES (128*AST*2 + 2*64*BST*2)   // 69632

__device__ __align__(16) float    g_y[(size_t)NN * 512];
__device__ __align__(16) float    g_h[(size_t)NN * 64];
__device__ __align__(16) unsigned g_cnt[NSEG];
__device__ __align__(16) unsigned g_off[NSEG + 1];
__device__ __align__(16) unsigned g_woff[NSEG];
__device__ __align__(16) unsigned g_bsum[512];
__device__ __align__(16) int      g_ssrc[EE];     // sorted by (dst,rel): src*8+rel
__device__ __align__(16) float    g_acc[128];
__device__ __align__(16) float    g_scale[64];
__device__ __align__(16) float    g_shift[64];
__device__ __align__(16) __nv_bfloat16 g_wp1[576 * KW];
__device__ __align__(16) __nv_bfloat16 g_wp2[576 * KW];

// ---------------- prep ----------------
__global__ void hist_kernel(const int* __restrict__ ei, const int* __restrict__ et,
                            unsigned* __restrict__ cnt) {
    int e = blockIdx.x * 256 + threadIdx.x;
    if (e >= EE) return;
    atomicAdd(cnt + ei[EE + e] * 8 + et[e], 1u);
}

__global__ void scan1(const unsigned* __restrict__ cnt, unsigned* __restrict__ off,
                      unsigned* __restrict__ bsum) {
    __shared__ unsigned sh[256];
    int t = threadIdx.x;
    int base = blockIdx.x * 2048 + t * 8;
    unsigned v[8], s = 0;
#pragma unroll
    for (int j = 0; j < 8; j++) { v[j] = (base + j < NSEG) ? cnt[base + j] : 0u; s += v[j]; }
    sh[t] = s; __syncthreads();
    for (int d = 1; d < 256; d <<= 1) {
        unsigned x = (t >= d) ? sh[t - d] : 0u;
        __syncthreads(); sh[t] += x; __syncthreads();
    }
    if (t == 255) bsum[blockIdx.x] = sh[255];
    unsigned run = sh[t] - s;
#pragma unroll
    for (int j = 0; j < 8; j++)
        if (base + j < NSEG) { off[base + j] = run; run += v[j]; }
}

__global__ void scan2(unsigned* bsum, int nb) {
    __shared__ unsigned sh[512];
    int t = threadIdx.x;
    unsigned v = (t < nb) ? bsum[t] : 0u;
    sh[t] = v; __syncthreads();
    for (int d = 1; d < 512; d <<= 1) {
        unsigned x = (t >= d) ? sh[t - d] : 0u;
        __syncthreads(); sh[t] += x; __syncthreads();
    }
    if (t < nb) bsum[t] = sh[t] - v;
}

__global__ void scan3(unsigned* __restrict__ off, unsigned* __restrict__ woff,
                      const unsigned* __restrict__ bsum) {
    int i = blockIdx.x * 256 + threadIdx.x;
    if (i < NSEG) { unsigned o = off[i] + bsum[i >> 11]; off[i] = o; woff[i] = o; }
    if (i == 0) off[NSEG] = EE;
}

__global__ void sort_kernel(const int* __restrict__ ei, const int* __restrict__ et,
                            unsigned* __restrict__ woff, int* __restrict__ ssrc) {
    int e = blockIdx.x * 256 + threadIdx.x;
    if (e >= EE) return;
    int r = et[e];
    int b = ei[EE + e] * 8 + r;
    unsigned pos = atomicAdd(woff + b, 1u);
    ssrc[pos] = ei[e] * 8 + r;
}

// pack W[r,d,o] (+root r==8) -> wp[j=r*64+o][k]: k<64 hi(d=k), else lo(d=k-64)
__global__ void prep_w(const float* __restrict__ w, const float* __restrict__ root,
                       __nv_bfloat16* __restrict__ wp) {
    int i = blockIdx.x * 256 + threadIdx.x;
    if (i >= 576 * KW) return;
    int j = i / KW, k = i % KW;
    int r = j >> 6, o = j & 63;
    int d = k & 63;
    float v = (r < 8) ? w[((size_t)r * 64 + d) * 64 + o] : root[(size_t)d * 64 + o];
    __nv_bfloat16 hi = __float2bfloat16(v);
    wp[i] = (k < 64) ? hi : __float2bfloat16(v - __bfloat162float(hi));
}

// ---------------- GEMM ----------------
__device__ __forceinline__ void cp16(void* dst, const void* src) {
    unsigned s = (unsigned)__cvta_generic_to_shared(dst);
    asm volatile("cp.async.cg.shared.global [%0], [%1], 16;" :: "r"(s), "l"(src));
}

__device__ __forceinline__ void issue_b_chunk(__nv_bfloat16* bbuf,
                                              const __nv_bfloat16* wp, int nc, int tid) {
    const __nv_bfloat16* src0 = wp + (size_t)nc * 64 * KW;
#pragma unroll
    for (int i = 0; i < 4; i++) {
        int t = tid + i * 256;          // 1024 = 64 rows x 16 segs
        int j = t >> 4, sg = t & 15;
        cp16(bbuf + j * BST + sg * 8, src0 + j * KW + sg * 8);
    }
}

#define MMA16816(c0,c1,c2,c3,a0,a1,a2,a3,b0,b1)                                     \
    asm volatile("mma.sync.aligned.m16n8k16.row.col.f32.bf16.bf16.f32 "             \
                 "{%0,%1,%2,%3},{%4,%5,%6,%7},{%8,%9},{%0,%1,%2,%3};"               \
                 : "+f"(c0), "+f"(c1), "+f"(c2), "+f"(c3)                           \
                 : "r"(a0), "r"(a1), "r"(a2), "r"(a3), "r"(b0), "r"(b1))

template <bool APPLY_BN>
__global__ void __launch_bounds__(256, 3)
gemm_kernel(const float* __restrict__ X, const __nv_bfloat16* __restrict__ WP,
            const float* __restrict__ bias,
            const float* __restrict__ bnscale, const float* __restrict__ bnshift,
            float* __restrict__ Y, float* __restrict__ OUT) {
    extern __shared__ char smem[];
    __nv_bfloat16* As = (__nv_bfloat16*)smem;                      // [128][AST]
    __nv_bfloat16* Bs = (__nv_bfloat16*)(smem + 128 * AST * 2);    // 2 x [64][BST]

    const int tid = threadIdx.x;
    const int wid = tid >> 5, lane = tid & 31;
    const int g = lane >> 2, tig = lane & 3;
    const int warpM = wid & 3, warpN = wid >> 2;
    const int mbase = blockIdx.x * 128;

    for (int it = tid; it < 128 * 32; it += 256) {
        int row = it >> 5, dp = it & 31;
        int grow = mbase + row;
        float2 v = make_float2(0.f, 0.f);
        if (grow < NN) v = *(const float2*)(X + (size_t)grow * 64 + dp * 2);
        if (APPLY_BN) {
            v.x = fmaxf(v.x * bnscale[dp * 2]     + bnshift[dp * 2], 0.f);
            v.y = fmaxf(v.y * bnscale[dp * 2 + 1] + bnshift[dp * 2 + 1], 0.f);
        }
        __nv_bfloat162 hi, lo;
        hi.x = __float2bfloat16(v.x); hi.y = __float2bfloat16(v.y);
        lo.x = __float2bfloat16(v.x - __bfloat162float(hi.x));
        lo.y = __float2bfloat16(v.y - __bfloat162float(hi.y));
        __nv_bfloat162* arow = (__nv_bfloat162*)(As + row * AST);
        arow[dp] = hi; arow[32 + dp] = lo;
    }

    issue_b_chunk(Bs, WP, 0, tid);
    asm volatile("cp.async.commit_group;");

    float c[2][4][4];
#pragma unroll
    for (int a = 0; a < 2; a++)
#pragma unroll
        for (int b = 0; b < 4; b++)
#pragma unroll
            for (int k = 0; k < 4; k++) c[a][b][k] = 0.f;

    for (int nc = 0; nc < 9; nc++) {
        if (nc + 1 < 9) {
            issue_b_chunk(Bs + ((nc + 1) & 1) * 64 * BST, WP, nc + 1, tid);
            asm volatile("cp.async.commit_group;");
            asm volatile("cp.async.wait_group 1;");
        } else {
            asm volatile("cp.async.wait_group 0;");
        }
        __syncthreads();

        const __nv_bfloat16* Bb = Bs + (nc & 1) * 64 * BST + (warpN * 32 + g) * BST;
#pragma unroll
        for (int term = 0; term < 3; term++) {
            // term0: Ah*Bh, term1: Al*Bh, term2: Ah*Bl
            const __nv_bfloat16* a0p = As + (warpM * 32 + g) * AST
                                          + ((term == 1) ? 64 : 0);
            const int bko = (term == 2) ? 64 : 0;
#pragma unroll
            for (int kt = 0; kt < 4; kt++) {
                const int kc = kt * 16 + 2 * tig;
                unsigned a[2][4], b[4][2];
#pragma unroll
                for (int mt = 0; mt < 2; mt++) {
                    const __nv_bfloat16* ap = a0p + mt * 16 * AST + kc;
                    a[mt][0] = *(const unsigned*)(ap);
                    a[mt][2] = *(const unsigned*)(ap + 8);
                    a[mt][1] = *(const unsigned*)(ap + 8 * AST);
                    a[mt][3] = *(const unsigned*)(ap + 8 * AST + 8);
                }
#pragma unroll
                for (int nt = 0; nt < 4; nt++) {
                    const __nv_bfloat16* bp = Bb + nt * 8 * BST + bko + kc;
                    b[nt][0] = *(const unsigned*)(bp);
                    b[nt][1] = *(const unsigned*)(bp + 8);
                }
#pragma unroll
                for (int mt = 0; mt < 2; mt++)
#pragma unroll
                    for (int nt = 0; nt < 4; nt++)
                        MMA16816(c[mt][nt][0], c[mt][nt][1], c[mt][nt][2], c[mt][nt][3],
                                 a[mt][0], a[mt][1], a[mt][2], a[mt][3],
                                 b[nt][0], b[nt][1]);
            }
        }
        __syncthreads();

#pragma unroll
        for (int mt = 0; mt < 2; mt++)
#pragma unroll
            for (int nt = 0; nt < 4; nt++) {
                float* cc = c[mt][nt];
                int row = mbase + warpM * 32 + mt * 16 + g;
                int col = warpN * 32 + nt * 8 + 2 * tig;
                if (nc < 8) {
                    size_t base = (size_t)row * 512 + nc * 64 + col;
                    if (row < NN)     *(float2*)(Y + base)           = make_float2(cc[0], cc[1]);
                    if (row + 8 < NN) *(float2*)(Y + base + 8 * 512) = make_float2(cc[2], cc[3]);
                } else {
                    float2 bb = *(const float2*)(bias + col);
                    if (row < NN)
                        *(float2*)(OUT + (size_t)row * 64 + col) = make_float2(cc[0] + bb.x, cc[1] + bb.y);
                    if (row + 8 < NN)
                        *(float2*)(OUT + (size_t)(row + 8) * 64 + col) = make_float2(cc[2] + bb.x, cc[3] + bb.y);
                }
                cc[0] = cc[1] = cc[2] = cc[3] = 0.f;
            }
    }
}

// ---------------- scatter: warp-per-dst segment reduce, no atomics ----------------
__global__ void __launch_bounds__(256)
scatter_kernel(const float* __restrict__ Y, const unsigned* __restrict__ off,
               const int* __restrict__ ssrc, float* __restrict__ OUT) {
    int node = blockIdx.x * 8 + (threadIdx.x >> 5);
    if (node >= NN) return;
    int lane = threadIdx.x & 31;

    unsigned ov = (lane < 9) ? __ldg(off + (size_t)node * 8 + lane) : 0u;
    unsigned onext = __shfl_down_sync(0xffffffffu, ov, 1);
    float invv = 1.0f / fmaxf((float)(onext - ov), 1.0f);   // valid for lane<8
    unsigned o0 = __shfl_sync(0xffffffffu, ov, 0);
    unsigned o8 = __shfl_sync(0xffffffffu, ov, 8);

    float accx = 0.f, accy = 0.f;
    for (unsigned e = o0; e < o8; e += 4) {
        int sa[4];
#pragma unroll
        for (int j = 0; j < 4; j++)
            sa[j] = (e + j < o8) ? __ldg(ssrc + e + j) : -1;
        float2 v[4];
#pragma unroll
        for (int j = 0; j < 4; j++) {
            v[j] = make_float2(0.f, 0.f);
            if (sa[j] >= 0)
                v[j] = *(const float2*)(Y + (size_t)sa[j] * 64 + lane * 2);
        }
#pragma unroll
        for (int j = 0; j < 4; j++) {
            if (sa[j] >= 0) {
                float iv = __shfl_sync(0xffffffffu, invv, sa[j] & 7);
                accx += v[j].x * iv; accy += v[j].y * iv;
            }
        }
    }
    float2* op = (float2*)(OUT + (size_t)node * 64 + lane * 2);
    float2 cur = *op;
    *op = make_float2(cur.x + accx, cur.y + accy);
}

// ---------------- batch norm ----------------
__global__ void bn_stats(const float* __restrict__ H, float* __restrict__ acc) {
    int ch = threadIdx.x & 63, ry = threadIdx.x >> 6;
    float s = 0.f, q = 0.f;
    for (int r = blockIdx.x * 4 + ry; r < NN; r += gridDim.x * 4) {
        float v = H[(size_t)r * 64 + ch];
        s += v; q += v * v;
    }
    __shared__ float sh[2][4][64];
    sh[0][ry][ch] = s; sh[1][ry][ch] = q;
    __syncthreads();
    if (ry == 0) {
        s = sh[0][0][ch] + sh[0][1][ch] + sh[0][2][ch] + sh[0][3][ch];
        q = sh[1][0][ch] + sh[1][1][ch] + sh[1][2][ch] + sh[1][3][ch];
        atomicAdd(acc + ch, s);
        atomicAdd(acc + 64 + ch, q);
    }
}

__global__ void bn_final(const float* __restrict__ acc, const float* __restrict__ gamma,
                         const float* __restrict__ beta,
                         float* __restrict__ scale, float* __restrict__ shift) {
    int ch = threadIdx.x;
    if (ch >= 64) return;
    const float invN = 1.0f / (float)NN;
    float mu = acc[ch] * invN;
    float var = acc[64 + ch] * invN - mu * mu;
    float sc = gamma[ch] * rsqrtf(var + 1e-5f);
    scale[ch] = sc;
    shift[ch] = beta[ch] - mu * sc;
}

// ---------------- launcher ----------------
extern "C" void kernel_launch(void* const* d_in, const int* in_sizes, int n_in,
                              void* d_out, int out_size) {
    const float* x      = (const float*)d_in[0];
    const int*   ei     = (const int*)d_in[1];
    const int*   etype  = (const int*)d_in[2];
    const float* w1     = (const float*)d_in[3];
    const float* root1  = (const float*)d_in[4];
    const float* b1     = (const float*)d_in[5];
    const float* gamma1 = (const float*)d_in[6];
    const float* beta1  = (const float*)d_in[7];
    const float* w2     = (const float*)d_in[8];
    const float* root2  = (const float*)d_in[9];
    const float* b2     = (const float*)d_in[10];
    float* out = (float*)d_out;

    float *y, *h, *acc, *scale, *shift;
    unsigned *cnt, *off, *woff, *bsum;
    int *ssrc;
    __nv_bfloat16 *wp1, *wp2;
    cudaGetSymbolAddress((void**)&y, g_y);
    cudaGetSymbolAddress((void**)&h, g_h);
    cudaGetSymbolAddress((void**)&cnt, g_cnt);
    cudaGetSymbolAddress((void**)&off, g_off);
    cudaGetSymbolAddress((void**)&woff, g_woff);
    cudaGetSymbolAddress((void**)&bsum, g_bsum);
    cudaGetSymbolAddress((void**)&ssrc, g_ssrc);
    cudaGetSymbolAddress((void**)&acc, g_acc);
    cudaGetSymbolAddress((void**)&scale, g_scale);
    cudaGetSymbolAddress((void**)&shift, g_shift);
    cudaGetSymbolAddress((void**)&wp1, g_wp1);
    cudaGetSymbolAddress((void**)&wp2, g_wp2);

    cudaFuncSetAttribute(gemm_kernel<false>, cudaFuncAttributeMaxDynamicSharedMemorySize, SMEM_BYTES);
    cudaFuncSetAttribute(gemm_kernel<true>,  cudaFuncAttributeMaxDynamicSharedMemorySize, SMEM_BYTES);

    const int MT = (NN + 127) / 128;           // 782
    const int NB1 = (NSEG + 2047) / 2048;      // 391

    cudaMemsetAsync(cnt, 0, NSEG * sizeof(unsigned), 0);
    cudaMemsetAsync(acc, 0, 128 * sizeof(float), 0);

    prep_w<<<(576 * KW + 255) / 256, 256>>>(w1, root1, wp1);   // 1
    prep_w<<<(576 * KW + 255) / 256, 256>>>(w2, root2, wp2);   // 2
    hist_kernel<<<(EE + 255) / 256, 256>>>(ei, etype, cnt);    // 3
    gemm_kernel<false><<<MT, 256, SMEM_BYTES>>>(x, wp1, b1, nullptr, nullptr, y, h); // 4 (profiled)
    scan1<<<NB1, 256>>>(cnt, off, bsum);                       // 5
    scan2<<<1, 512>>>(bsum, NB1);                              // 6
    scan3<<<(NSEG + 255) / 256, 256>>>(off, woff, bsum);       // 7
    sort_kernel<<<(EE + 255) / 256, 256>>>(ei, etype, woff, ssrc); // 8
    scatter_kernel<<<(NN + 7) / 8, 256>>>(y, off, ssrc, h);    // 9
    bn_stats<<<1024, 256>>>(h, acc);                           // 10
    bn_final<<<1, 64>>>(acc, gamma1, beta1, scale, shift);     // 11
    gemm_kernel<true><<<MT, 256, SMEM_BYTES>>>(h, wp2, b2, scale, shift, y, out); // 12
    scatter_kernel<<<(NN + 7) / 8, 256>>>(y, off, ssrc, out);  // 13
}

// round 9
// speedup vs baseline: 1.4128x; 1.1621x over previous
#include <cuda_runtime.h>
#include <cuda_bf16.h>

#define NN 100000
#define EE 1600000
#define NSEG (NN * 8)
#define AST 136                 // A smem row stride (bf16): [Ah 64 | Al 64 | pad 8]
#define BST 136                 // B smem row stride (bf16): [Bh 64 | Bl 64 | pad 8]
#define KW 128                  // packed W row: [0,64)=hi, [64,128)=lo
#define SMEM_BYTES (64*AST*2 + 2*64*BST*2)    // 52224

__device__ __align__(16) float    g_y[(size_t)NN * 512];
__device__ __align__(16) float    g_h[(size_t)NN * 64];
__device__ __align__(16) unsigned g_cnt[NSEG];
__device__ __align__(16) unsigned g_off[NSEG + 1];
__device__ __align__(16) unsigned g_woff[NSEG];
__device__ __align__(16) unsigned g_bsum[512];
__device__ __align__(16) int      g_ssrc[EE];     // sorted by (dst,rel): src*8+rel
__device__ __align__(16) float    g_acc[128];
__device__ __align__(16) float    g_scale[64];
__device__ __align__(16) float    g_shift[64];
__device__ __align__(16) __nv_bfloat16 g_wp1[576 * KW];
__device__ __align__(16) __nv_bfloat16 g_wp2[576 * KW];

// ---------------- prep ----------------
__global__ void hist_kernel(const int* __restrict__ ei, const int* __restrict__ et,
                            unsigned* __restrict__ cnt) {
    int e = blockIdx.x * 256 + threadIdx.x;
    if (e >= EE) return;
    atomicAdd(cnt + ei[EE + e] * 8 + et[e], 1u);
}

__global__ void scan1(const unsigned* __restrict__ cnt, unsigned* __restrict__ off,
                      unsigned* __restrict__ bsum) {
    __shared__ unsigned sh[256];
    int t = threadIdx.x;
    int base = blockIdx.x * 2048 + t * 8;
    unsigned v[8], s = 0;
#pragma unroll
    for (int j = 0; j < 8; j++) { v[j] = (base + j < NSEG) ? cnt[base + j] : 0u; s += v[j]; }
    sh[t] = s; __syncthreads();
    for (int d = 1; d < 256; d <<= 1) {
        unsigned x = (t >= d) ? sh[t - d] : 0u;
        __syncthreads(); sh[t] += x; __syncthreads();
    }
    if (t == 255) bsum[blockIdx.x] = sh[255];
    unsigned run = sh[t] - s;
#pragma unroll
    for (int j = 0; j < 8; j++)
        if (base + j < NSEG) { off[base + j] = run; run += v[j]; }
}

__global__ void scan2(unsigned* bsum, int nb) {
    __shared__ unsigned sh[512];
    int t = threadIdx.x;
    unsigned v = (t < nb) ? bsum[t] : 0u;
    sh[t] = v; __syncthreads();
    for (int d = 1; d < 512; d <<= 1) {
        unsigned x = (t >= d) ? sh[t - d] : 0u;
        __syncthreads(); sh[t] += x; __syncthreads();
    }
    if (t < nb) bsum[t] = sh[t] - v;
}

__global__ void scan3(unsigned* __restrict__ off, unsigned* __restrict__ woff,
                      const unsigned* __restrict__ bsum) {
    int i = blockIdx.x * 256 + threadIdx.x;
    if (i < NSEG) { unsigned o = off[i] + bsum[i >> 11]; off[i] = o; woff[i] = o; }
    if (i == 0) off[NSEG] = EE;
}

__global__ void sort_kernel(const int* __restrict__ ei, const int* __restrict__ et,
                            unsigned* __restrict__ woff, int* __restrict__ ssrc) {
    int e = blockIdx.x * 256 + threadIdx.x;
    if (e >= EE) return;
    int r = et[e];
    int b = ei[EE + e] * 8 + r;
    unsigned pos = atomicAdd(woff + b, 1u);
    ssrc[pos] = ei[e] * 8 + r;
}

// pack W[r,d,o] (+root r==8) -> wp[j=r*64+o][k]: k<64 hi(d=k), else lo(d=k-64)
__global__ void prep_w(const float* __restrict__ w, const float* __restrict__ root,
                       __nv_bfloat16* __restrict__ wp) {
    int i = blockIdx.x * 256 + threadIdx.x;
    if (i >= 576 * KW) return;
    int j = i / KW, k = i % KW;
    int r = j >> 6, o = j & 63;
    int d = k & 63;
    float v = (r < 8) ? w[((size_t)r * 64 + d) * 64 + o] : root[(size_t)d * 64 + o];
    __nv_bfloat16 hi = __float2bfloat16(v);
    wp[i] = (k < 64) ? hi : __float2bfloat16(v - __bfloat162float(hi));
}

// ---------------- GEMM: 64-row blocks, register-resident A ----------------
__device__ __forceinline__ void cp16(void* dst, const void* src) {
    unsigned s = (unsigned)__cvta_generic_to_shared(dst);
    asm volatile("cp.async.cg.shared.global [%0], [%1], 16;" :: "r"(s), "l"(src));
}

__device__ __forceinline__ void issue_b_chunk(__nv_bfloat16* bbuf,
                                              const __nv_bfloat16* wp, int nc, int tid) {
    const __nv_bfloat16* src0 = wp + (size_t)nc * 64 * KW;
#pragma unroll
    for (int i = 0; i < 4; i++) {
        int t = tid + i * 256;          // 1024 = 64 rows x 16 segs of 8 bf16
        int j = t >> 4, sg = t & 15;
        cp16(bbuf + j * BST + sg * 8, src0 + j * KW + sg * 8);
    }
}

#define MMA16816(c0,c1,c2,c3,a0,a1,a2,a3,b0,b1)                                     \
    asm volatile("mma.sync.aligned.m16n8k16.row.col.f32.bf16.bf16.f32 "             \
                 "{%0,%1,%2,%3},{%4,%5,%6,%7},{%8,%9},{%0,%1,%2,%3};"               \
                 : "+f"(c0), "+f"(c1), "+f"(c2), "+f"(c3)                           \
                 : "r"(a0), "r"(a1), "r"(a2), "r"(a3), "r"(b0), "r"(b1))

template <bool APPLY_BN>
__global__ void __launch_bounds__(256)
gemm_kernel(const float* __restrict__ X, const __nv_bfloat16* __restrict__ WP,
            const float* __restrict__ bias,
            const float* __restrict__ bnscale, const float* __restrict__ bnshift,
            float* __restrict__ Y, float* __restrict__ OUT) {
    extern __shared__ char smem[];
    __nv_bfloat16* As = (__nv_bfloat16*)smem;                      // [64][AST]
    __nv_bfloat16* Bs = (__nv_bfloat16*)(smem + 64 * AST * 2);     // 2 x [64][BST]

    const int tid = threadIdx.x;
    const int wid = tid >> 5, lane = tid & 31;
    const int g = lane >> 2, tig = lane & 3;
    const int warpM = wid & 3, warpN = wid >> 2;      // m16 x n32 warp tiles
    const int mbase = blockIdx.x * 64;

    issue_b_chunk(Bs, WP, 0, tid);
    asm volatile("cp.async.commit_group;");

    // A fill: 64 rows x 32 float2
    for (int it = tid; it < 64 * 32; it += 256) {
        int row = it >> 5, dp = it & 31;
        int grow = mbase + row;
        float2 v = make_float2(0.f, 0.f);
        if (grow < NN) v = *(const float2*)(X + (size_t)grow * 64 + dp * 2);
        if (APPLY_BN) {
            v.x = fmaxf(v.x * bnscale[dp * 2]     + bnshift[dp * 2], 0.f);
            v.y = fmaxf(v.y * bnscale[dp * 2 + 1] + bnshift[dp * 2 + 1], 0.f);
        }
        __nv_bfloat162 hi, lo;
        hi.x = __float2bfloat16(v.x); hi.y = __float2bfloat16(v.y);
        lo.x = __float2bfloat16(v.x - __bfloat162float(hi.x));
        lo.y = __float2bfloat16(v.y - __bfloat162float(hi.y));
        __nv_bfloat162* arow = (__nv_bfloat162*)(As + row * AST);
        arow[dp] = hi; arow[32 + dp] = lo;
    }
    __syncthreads();

    // A fragments -> registers ONCE (reused by all 9 chunks x 3 terms)
    unsigned ah[4][4], al[4][4];
    {
        const __nv_bfloat16* ap0 = As + (warpM * 16 + g) * AST;
#pragma unroll
        for (int kt = 0; kt < 4; kt++) {
            const int kc = kt * 16 + 2 * tig;
            ah[kt][0] = *(const unsigned*)(ap0 + kc);
            ah[kt][2] = *(const unsigned*)(ap0 + kc + 8);
            ah[kt][1] = *(const unsigned*)(ap0 + 8 * AST + kc);
            ah[kt][3] = *(const unsigned*)(ap0 + 8 * AST + kc + 8);
            al[kt][0] = *(const unsigned*)(ap0 + 64 + kc);
            al[kt][2] = *(const unsigned*)(ap0 + 64 + kc + 8);
            al[kt][1] = *(const unsigned*)(ap0 + 8 * AST + 64 + kc);
            al[kt][3] = *(const unsigned*)(ap0 + 8 * AST + 64 + kc + 8);
        }
    }

    float c[4][4];
#pragma unroll
    for (int nt = 0; nt < 4; nt++)
#pragma unroll
        for (int k = 0; k < 4; k++) c[nt][k] = 0.f;

    for (int nc = 0; nc < 9; nc++) {
        if (nc + 1 < 9) {
            issue_b_chunk(Bs + ((nc + 1) & 1) * 64 * BST, WP, nc + 1, tid);
            asm volatile("cp.async.commit_group;");
            asm volatile("cp.async.wait_group 1;");
        } else {
            asm volatile("cp.async.wait_group 0;");
        }
        __syncthreads();

        const __nv_bfloat16* Bb = Bs + (nc & 1) * 64 * BST + (warpN * 32 + g) * BST;
#pragma unroll
        for (int kt = 0; kt < 4; kt++) {
            const int kc = kt * 16 + 2 * tig;
            unsigned bh[4][2], bl[4][2];
#pragma unroll
            for (int nt = 0; nt < 4; nt++) {
                const __nv_bfloat16* bp = Bb + nt * 8 * BST + kc;
                bh[nt][0] = *(const unsigned*)(bp);
                bh[nt][1] = *(const unsigned*)(bp + 8);
                bl[nt][0] = *(const unsigned*)(bp + 64);
                bl[nt][1] = *(const unsigned*)(bp + 72);
            }
#pragma unroll
            for (int nt = 0; nt < 4; nt++) {
                MMA16816(c[nt][0], c[nt][1], c[nt][2], c[nt][3],
                         ah[kt][0], ah[kt][1], ah[kt][2], ah[kt][3], bh[nt][0], bh[nt][1]);
                MMA16816(c[nt][0], c[nt][1], c[nt][2], c[nt][3],
                         al[kt][0], al[kt][1], al[kt][2], al[kt][3], bh[nt][0], bh[nt][1]);
                MMA16816(c[nt][0], c[nt][1], c[nt][2], c[nt][3],
                         ah[kt][0], ah[kt][1], ah[kt][2], ah[kt][3], bl[nt][0], bl[nt][1]);
            }
        }
        __syncthreads();

        // epilogue for this 64-col chunk
        int row = mbase + warpM * 16 + g;
#pragma unroll
        for (int nt = 0; nt < 4; nt++) {
            int col = warpN * 32 + nt * 8 + 2 * tig;
            if (nc < 8) {
                size_t base = (size_t)row * 512 + nc * 64 + col;
                if (row < NN)     *(float2*)(Y + base)           = make_float2(c[nt][0], c[nt][1]);
                if (row + 8 < NN) *(float2*)(Y + base + 8 * 512) = make_float2(c[nt][2], c[nt][3]);
            } else {
                float2 bb = *(const float2*)(bias + col);
                if (row < NN)
                    *(float2*)(OUT + (size_t)row * 64 + col) = make_float2(c[nt][0] + bb.x, c[nt][1] + bb.y);
                if (row + 8 < NN)
                    *(float2*)(OUT + (size_t)(row + 8) * 64 + col) = make_float2(c[nt][2] + bb.x, c[nt][3] + bb.y);
            }
            c[nt][0] = c[nt][1] = c[nt][2] = c[nt][3] = 0.f;
        }
    }
}

// ---------------- scatter: warp-per-dst segment reduce, no atomics ----------------
__global__ void __launch_bounds__(256)
scatter_kernel(const float* __restrict__ Y, const unsigned* __restrict__ off,
               const int* __restrict__ ssrc, float* __restrict__ OUT) {
    int node = blockIdx.x * 8 + (threadIdx.x >> 5);
    if (node >= NN) return;
    int lane = threadIdx.x & 31;

    unsigned ov = (lane < 9) ? __ldg(off + (size_t)node * 8 + lane) : 0u;
    unsigned onext = __shfl_down_sync(0xffffffffu, ov, 1);
    float invv = 1.0f / fmaxf((float)(onext - ov), 1.0f);   // valid for lane<8
    unsigned o0 = __shfl_sync(0xffffffffu, ov, 0);
    unsigned o8 = __shfl_sync(0xffffffffu, ov, 8);

    float accx = 0.f, accy = 0.f;
    for (unsigned e = o0; e < o8; e += 4) {
        int sa[4];
#pragma unroll
        for (int j = 0; j < 4; j++)
            sa[j] = (e + j < o8) ? __ldg(ssrc + e + j) : -1;
        float2 v[4];
#pragma unroll
        for (int j = 0; j < 4; j++) {
            v[j] = make_float2(0.f, 0.f);
            if (sa[j] >= 0)
                v[j] = *(const float2*)(Y + (size_t)sa[j] * 64 + lane * 2);
        }
#pragma unroll
        for (int j = 0; j < 4; j++) {
            if (sa[j] >= 0) {
                float iv = __shfl_sync(0xffffffffu, invv, sa[j] & 7);
                accx += v[j].x * iv; accy += v[j].y * iv;
            }
        }
    }
    float2* op = (float2*)(OUT + (size_t)node * 64 + lane * 2);
    float2 cur = *op;
    *op = make_float2(cur.x + accx, cur.y + accy);
}

// ---------------- batch norm ----------------
__global__ void bn_stats(const float* __restrict__ H, float* __restrict__ acc) {
    int ch = threadIdx.x & 63, ry = threadIdx.x >> 6;
    float s = 0.f, q = 0.f;
    for (int r = blockIdx.x * 4 + ry; r < NN; r += gridDim.x * 4) {
        float v = H[(size_t)r * 64 + ch];
        s += v; q += v * v;
    }
    __shared__ float sh[2][4][64];
    sh[0][ry][ch] = s; sh[1][ry][ch] = q;
    __syncthreads();
    if (ry == 0) {
        s = sh[0][0][ch] + sh[0][1][ch] + sh[0][2][ch] + sh[0][3][ch];
        q = sh[1][0][ch] + sh[1][1][ch] + sh[1][2][ch] + sh[1][3][ch];
        atomicAdd(acc + ch, s);
        atomicAdd(acc + 64 + ch, q);
    }
}

__global__ void bn_final(const float* __restrict__ acc, const float* __restrict__ gamma,
                         const float* __restrict__ beta,
                         float* __restrict__ scale, float* __restrict__ shift) {
    int ch = threadIdx.x;
    if (ch >= 64) return;
    const float invN = 1.0f / (float)NN;
    float mu = acc[ch] * invN;
    float var = acc[64 + ch] * invN - mu * mu;
    float sc = gamma[ch] * rsqrtf(var + 1e-5f);
    scale[ch] = sc;
    shift[ch] = beta[ch] - mu * sc;
}

// ---------------- launcher ----------------
extern "C" void kernel_launch(void* const* d_in, const int* in_sizes, int n_in,
                              void* d_out, int out_size) {
    const float* x      = (const float*)d_in[0];
    const int*   ei     = (const int*)d_in[1];
    const int*   etype  = (const int*)d_in[2];
    const float* w1     = (const float*)d_in[3];
    const float* root1  = (const float*)d_in[4];
    const float* b1     = (const float*)d_in[5];
    const float* gamma1 = (const float*)d_in[6];
    const float* beta1  = (const float*)d_in[7];
    const float* w2     = (const float*)d_in[8];
    const float* root2  = (const float*)d_in[9];
    const float* b2     = (const float*)d_in[10];
    float* out = (float*)d_out;

    float *y, *h, *acc, *scale, *shift;
    unsigned *cnt, *off, *woff, *bsum;
    int *ssrc;
    __nv_bfloat16 *wp1, *wp2;
    cudaGetSymbolAddress((void**)&y, g_y);
    cudaGetSymbolAddress((void**)&h, g_h);
    cudaGetSymbolAddress((void**)&cnt, g_cnt);
    cudaGetSymbolAddress((void**)&off, g_off);
    cudaGetSymbolAddress((void**)&woff, g_woff);
    cudaGetSymbolAddress((void**)&bsum, g_bsum);
    cudaGetSymbolAddress((void**)&ssrc, g_ssrc);
    cudaGetSymbolAddress((void**)&acc, g_acc);
    cudaGetSymbolAddress((void**)&scale, g_scale);
    cudaGetSymbolAddress((void**)&shift, g_shift);
    cudaGetSymbolAddress((void**)&wp1, g_wp1);
    cudaGetSymbolAddress((void**)&wp2, g_wp2);

    cudaFuncSetAttribute(gemm_kernel<false>, cudaFuncAttributeMaxDynamicSharedMemorySize, SMEM_BYTES);
    cudaFuncSetAttribute(gemm_kernel<true>,  cudaFuncAttributeMaxDynamicSharedMemorySize, SMEM_BYTES);

    const int MT = (NN + 63) / 64;             // 1563
    const int NB1 = (NSEG + 2047) / 2048;      // 391

    cudaMemsetAsync(cnt, 0, NSEG * sizeof(unsigned), 0);
    cudaMemsetAsync(acc, 0, 128 * sizeof(float), 0);

    prep_w<<<(576 * KW + 255) / 256, 256>>>(w1, root1, wp1);   // 1
    prep_w<<<(576 * KW + 255) / 256, 256>>>(w2, root2, wp2);   // 2
    hist_kernel<<<(EE + 255) / 256, 256>>>(ei, etype, cnt);    // 3
    gemm_kernel<false><<<MT, 256, SMEM_BYTES>>>(x, wp1, b1, nullptr, nullptr, y, h); // 4 (profiled)
    scan1<<<NB1, 256>>>(cnt, off, bsum);                       // 5
    scan2<<<1, 512>>>(bsum, NB1);                              // 6
    scan3<<<(NSEG + 255) / 256, 256>>>(off, woff, bsum);       // 7
    sort_kernel<<<(EE + 255) / 256, 256>>>(ei, etype, woff, ssrc); // 8
    scatter_kernel<<<(NN + 7) / 8, 256>>>(y, off, ssrc, h);    // 9
    bn_stats<<<1024, 256>>>(h, acc);                           // 10
    bn_final<<<1, 64>>>(acc, gamma1, beta1, scale, shift);     // 11
    gemm_kernel<true><<<MT, 256, SMEM_BYTES>>>(h, wp2, b2, scale, shift, y, out); // 12
    scatter_kernel<<<(NN + 7) / 8, 256>>>(y, off, ssrc, out);  // 13
}

// round 10
// speedup vs baseline: 1.5072x; 1.0668x over previous
#include <cuda_runtime.h>
#include <cuda_bf16.h>
#include <cuda_fp16.h>

#define NN 100000
#define EE 1600000
#define NSEG (NN * 8)
#define AST 136                 // A smem row stride (bf16): [Ah 64 | Al 64 | pad 8]
#define BST 136                 // B smem row stride (bf16): [Bh 64 | Bl 64 | pad 8]
#define KW 128                  // packed W row: [0,64)=hi, [64,128)=lo
#define SMEM_BYTES (64*AST*2 + 2*64*BST*2)    // 52224

__device__ __align__(16) __half   g_y[(size_t)NN * 512];   // fp16 Y: 102MB, ~L2-resident
__device__ __align__(16) float    g_h[(size_t)NN * 64];
__device__ __align__(16) unsigned g_cnt[NSEG];
__device__ __align__(16) unsigned g_off[NSEG + 1];
__device__ __align__(16) unsigned g_woff[NSEG];
__device__ __align__(16) unsigned g_bsum[512];
__device__ __align__(16) int      g_ssrc[EE];     // sorted by (dst,rel): src*8+rel
__device__ __align__(16) float    g_acc[128];
__device__ __align__(16) float    g_scale[64];
__device__ __align__(16) float    g_shift[64];
__device__ __align__(16) __nv_bfloat16 g_wp1[576 * KW];
__device__ __align__(16) __nv_bfloat16 g_wp2[576 * KW];

// ---------------- prep ----------------
__global__ void hist_kernel(const int* __restrict__ ei, const int* __restrict__ et,
                            unsigned* __restrict__ cnt) {
    int e = blockIdx.x * 256 + threadIdx.x;
    if (e >= EE) return;
    atomicAdd(cnt + ei[EE + e] * 8 + et[e], 1u);
}

__global__ void scan1(const unsigned* __restrict__ cnt, unsigned* __restrict__ off,
                      unsigned* __restrict__ bsum) {
    __shared__ unsigned sh[256];
    int t = threadIdx.x;
    int base = blockIdx.x * 2048 + t * 8;
    unsigned v[8], s = 0;
#pragma unroll
    for (int j = 0; j < 8; j++) { v[j] = (base + j < NSEG) ? cnt[base + j] : 0u; s += v[j]; }
    sh[t] = s; __syncthreads();
    for (int d = 1; d < 256; d <<= 1) {
        unsigned x = (t >= d) ? sh[t - d] : 0u;
        __syncthreads(); sh[t] += x; __syncthreads();
    }
    if (t == 255) bsum[blockIdx.x] = sh[255];
    unsigned run = sh[t] - s;
#pragma unroll
    for (int j = 0; j < 8; j++)
        if (base + j < NSEG) { off[base + j] = run; run += v[j]; }
}

__global__ void scan2(unsigned* bsum, int nb) {
    __shared__ unsigned sh[512];
    int t = threadIdx.x;
    unsigned v = (t < nb) ? bsum[t] : 0u;
    sh[t] = v; __syncthreads();
    for (int d = 1; d < 512; d <<= 1) {
        unsigned x = (t >= d) ? sh[t - d] : 0u;
        __syncthreads(); sh[t] += x; __syncthreads();
    }
    if (t < nb) bsum[t] = sh[t] - v;
}

__global__ void scan3(unsigned* __restrict__ off, unsigned* __restrict__ woff,
                      const unsigned* __restrict__ bsum) {
    int i = blockIdx.x * 256 + threadIdx.x;
    if (i < NSEG) { unsigned o = off[i] + bsum[i >> 11]; off[i] = o; woff[i] = o; }
    if (i == 0) off[NSEG] = EE;
}

__global__ void sort_kernel(const int* __restrict__ ei, const int* __restrict__ et,
                            unsigned* __restrict__ woff, int* __restrict__ ssrc) {
    int e = blockIdx.x * 256 + threadIdx.x;
    if (e >= EE) return;
    int r = et[e];
    int b = ei[EE + e] * 8 + r;
    unsigned pos = atomicAdd(woff + b, 1u);
    ssrc[pos] = ei[e] * 8 + r;
}

// pack W[r,d,o] (+root r==8) -> wp[j=r*64+o][k]: k<64 hi(d=k), else lo(d=k-64)
__global__ void prep_w(const float* __restrict__ w, const float* __restrict__ root,
                       __nv_bfloat16* __restrict__ wp) {
    int i = blockIdx.x * 256 + threadIdx.x;
    if (i >= 576 * KW) return;
    int j = i / KW, k = i % KW;
    int r = j >> 6, o = j & 63;
    int d = k & 63;
    float v = (r < 8) ? w[((size_t)r * 64 + d) * 64 + o] : root[(size_t)d * 64 + o];
    __nv_bfloat16 hi = __float2bfloat16(v);
    wp[i] = (k < 64) ? hi : __float2bfloat16(v - __bfloat162float(hi));
}

// ---------------- GEMM: 64-row blocks, register-resident A, fp16 Y out ----------------
__device__ __forceinline__ void cp16(void* dst, const void* src) {
    unsigned s = (unsigned)__cvta_generic_to_shared(dst);
    asm volatile("cp.async.cg.shared.global [%0], [%1], 16;" :: "r"(s), "l"(src));
}

__device__ __forceinline__ void issue_b_chunk(__nv_bfloat16* bbuf,
                                              const __nv_bfloat16* wp, int nc, int tid) {
    const __nv_bfloat16* src0 = wp + (size_t)nc * 64 * KW;
#pragma unroll
    for (int i = 0; i < 4; i++) {
        int t = tid + i * 256;          // 1024 = 64 rows x 16 segs of 8 bf16
        int j = t >> 4, sg = t & 15;
        cp16(bbuf + j * BST + sg * 8, src0 + j * KW + sg * 8);
    }
}

#define MMA16816(c0,c1,c2,c3,a0,a1,a2,a3,b0,b1)                                     \
    asm volatile("mma.sync.aligned.m16n8k16.row.col.f32.bf16.bf16.f32 "             \
                 "{%0,%1,%2,%3},{%4,%5,%6,%7},{%8,%9},{%0,%1,%2,%3};"               \
                 : "+f"(c0), "+f"(c1), "+f"(c2), "+f"(c3)                           \
                 : "r"(a0), "r"(a1), "r"(a2), "r"(a3), "r"(b0), "r"(b1))

template <bool APPLY_BN>
__global__ void __launch_bounds__(256)
gemm_kernel(const float* __restrict__ X, const __nv_bfloat16* __restrict__ WP,
            const float* __restrict__ bias,
            const float* __restrict__ bnscale, const float* __restrict__ bnshift,
            __half* __restrict__ Y, float* __restrict__ OUT) {
    extern __shared__ char smem[];
    __nv_bfloat16* As = (__nv_bfloat16*)smem;                      // [64][AST]
    __nv_bfloat16* Bs = (__nv_bfloat16*)(smem + 64 * AST * 2);     // 2 x [64][BST]

    const int tid = threadIdx.x;
    const int wid = tid >> 5, lane = tid & 31;
    const int g = lane >> 2, tig = lane & 3;
    const int warpM = wid & 3, warpN = wid >> 2;      // m16 x n32 warp tiles
    const int mbase = blockIdx.x * 64;

    issue_b_chunk(Bs, WP, 0, tid);
    asm volatile("cp.async.commit_group;");

    // A fill: 64 rows x 32 float2
    for (int it = tid; it < 64 * 32; it += 256) {
        int row = it >> 5, dp = it & 31;
        int grow = mbase + row;
        float2 v = make_float2(0.f, 0.f);
        if (grow < NN) v = *(const float2*)(X + (size_t)grow * 64 + dp * 2);
        if (APPLY_BN) {
            v.x = fmaxf(v.x * bnscale[dp * 2]     + bnshift[dp * 2], 0.f);
            v.y = fmaxf(v.y * bnscale[dp * 2 + 1] + bnshift[dp * 2 + 1], 0.f);
        }
        __nv_bfloat162 hi, lo;
        hi.x = __float2bfloat16(v.x); hi.y = __float2bfloat16(v.y);
        lo.x = __float2bfloat16(v.x - __bfloat162float(hi.x));
        lo.y = __float2bfloat16(v.y - __bfloat162float(hi.y));
        __nv_bfloat162* arow = (__nv_bfloat162*)(As + row * AST);
        arow[dp] = hi; arow[32 + dp] = lo;
    }
    __syncthreads();

    // A fragments -> registers ONCE (reused by all 9 chunks x 3 terms)
    unsigned ah[4][4], al[4][4];
    {
        const __nv_bfloat16* ap0 = As + (warpM * 16 + g) * AST;
#pragma unroll
        for (int kt = 0; kt < 4; kt++) {
            const int kc = kt * 16 + 2 * tig;
            ah[kt][0] = *(const unsigned*)(ap0 + kc);
            ah[kt][2] = *(const unsigned*)(ap0 + kc + 8);
            ah[kt][1] = *(const unsigned*)(ap0 + 8 * AST + kc);
            ah[kt][3] = *(const unsigned*)(ap0 + 8 * AST + kc + 8);
            al[kt][0] = *(const unsigned*)(ap0 + 64 + kc);
            al[kt][2] = *(const unsigned*)(ap0 + 64 + kc + 8);
            al[kt][1] = *(const unsigned*)(ap0 + 8 * AST + 64 + kc);
            al[kt][3] = *(const unsigned*)(ap0 + 8 * AST + 64 + kc + 8);
        }
    }

    float c[4][4];
#pragma unroll
    for (int nt = 0; nt < 4; nt++)
#pragma unroll
        for (int k = 0; k < 4; k++) c[nt][k] = 0.f;

    for (int nc = 0; nc < 9; nc++) {
        if (nc + 1 < 9) {
            issue_b_chunk(Bs + ((nc + 1) & 1) * 64 * BST, WP, nc + 1, tid);
            asm volatile("cp.async.commit_group;");
            asm volatile("cp.async.wait_group 1;");
        } else {
            asm volatile("cp.async.wait_group 0;");
        }
        __syncthreads();

        const __nv_bfloat16* Bb = Bs + (nc & 1) * 64 * BST + (warpN * 32 + g) * BST;
#pragma unroll
        for (int kt = 0; kt < 4; kt++) {
            const int kc = kt * 16 + 2 * tig;
            unsigned bh[4][2], bl[4][2];
#pragma unroll
            for (int nt = 0; nt < 4; nt++) {
                const __nv_bfloat16* bp = Bb + nt * 8 * BST + kc;
                bh[nt][0] = *(const unsigned*)(bp);
                bh[nt][1] = *(const unsigned*)(bp + 8);
                bl[nt][0] = *(const unsigned*)(bp + 64);
                bl[nt][1] = *(const unsigned*)(bp + 72);
            }
#pragma unroll
            for (int nt = 0; nt < 4; nt++) {
                MMA16816(c[nt][0], c[nt][1], c[nt][2], c[nt][3],
                         ah[kt][0], ah[kt][1], ah[kt][2], ah[kt][3], bh[nt][0], bh[nt][1]);
                MMA16816(c[nt][0], c[nt][1], c[nt][2], c[nt][3],
                         al[kt][0], al[kt][1], al[kt][2], al[kt][3], bh[nt][0], bh[nt][1]);
                MMA16816(c[nt][0], c[nt][1], c[nt][2], c[nt][3],
                         ah[kt][0], ah[kt][1], ah[kt][2], ah[kt][3], bl[nt][0], bl[nt][1]);
            }
        }
        __syncthreads();

        // epilogue for this 64-col chunk
        int row = mbase + warpM * 16 + g;
#pragma unroll
        for (int nt = 0; nt < 4; nt++) {
            int col = warpN * 32 + nt * 8 + 2 * tig;
            if (nc < 8) {
                size_t base = (size_t)row * 512 + nc * 64 + col;
                if (row < NN)
                    *(__half2*)(Y + base) = __floats2half2_rn(c[nt][0], c[nt][1]);
                if (row + 8 < NN)
                    *(__half2*)(Y + base + 8 * 512) = __floats2half2_rn(c[nt][2], c[nt][3]);
            } else {
                float2 bb = *(const float2*)(bias + col);
                if (row < NN)
                    *(float2*)(OUT + (size_t)row * 64 + col) = make_float2(c[nt][0] + bb.x, c[nt][1] + bb.y);
                if (row + 8 < NN)
                    *(float2*)(OUT + (size_t)(row + 8) * 64 + col) = make_float2(c[nt][2] + bb.x, c[nt][3] + bb.y);
            }
            c[nt][0] = c[nt][1] = c[nt][2] = c[nt][3] = 0.f;
        }
    }
}

// ---------------- scatter: warp-per-dst segment reduce, fp16 Y reads ----------------
__global__ void __launch_bounds__(256)
scatter_kernel(const __half* __restrict__ Y, const unsigned* __restrict__ off,
               const int* __restrict__ ssrc, float* __restrict__ OUT) {
    int node = blockIdx.x * 8 + (threadIdx.x >> 5);
    if (node >= NN) return;
    int lane = threadIdx.x & 31;

    unsigned ov = (lane < 9) ? __ldg(off + (size_t)node * 8 + lane) : 0u;
    unsigned onext = __shfl_down_sync(0xffffffffu, ov, 1);
    float invv = 1.0f / fmaxf((float)(onext - ov), 1.0f);   // valid for lane<8
    unsigned o0 = __shfl_sync(0xffffffffu, ov, 0);
    unsigned o8 = __shfl_sync(0xffffffffu, ov, 8);

    float accx = 0.f, accy = 0.f;
    for (unsigned e = o0; e < o8; e += 4) {
        int sa[4];
#pragma unroll
        for (int j = 0; j < 4; j++)
            sa[j] = (e + j < o8) ? __ldg(ssrc + e + j) : -1;
        float2 v[4];
#pragma unroll
        for (int j = 0; j < 4; j++) {
            v[j] = make_float2(0.f, 0.f);
            if (sa[j] >= 0) {
                __half2 hv = *(const __half2*)(Y + (size_t)sa[j] * 64 + lane * 2);
                v[j] = __half22float2(hv);
            }
        }
#pragma unroll
        for (int j = 0; j < 4; j++) {
            if (sa[j] >= 0) {
                float iv = __shfl_sync(0xffffffffu, invv, sa[j] & 7);
                accx += v[j].x * iv; accy += v[j].y * iv;
            }
        }
    }
    float2* op = (float2*)(OUT + (size_t)node * 64 + lane * 2);
    float2 cur = *op;
    *op = make_float2(cur.x + accx, cur.y + accy);
}

// ---------------- batch norm ----------------
__global__ void bn_stats(const float* __restrict__ H, float* __restrict__ acc) {
    int ch = threadIdx.x & 63, ry = threadIdx.x >> 6;
    float s = 0.f, q = 0.f;
    for (int r = blockIdx.x * 4 + ry; r < NN; r += gridDim.x * 4) {
        float v = H[(size_t)r * 64 + ch];
        s += v; q += v * v;
    }
    __shared__ float sh[2][4][64];
    sh[0][ry][ch] = s; sh[1][ry][ch] = q;
    __syncthreads();
    if (ry == 0) {
        s = sh[0][0][ch] + sh[0][1][ch] + sh[0][2][ch] + sh[0][3][ch];
        q = sh[1][0][ch] + sh[1][1][ch] + sh[1][2][ch] + sh[1][3][ch];
        atomicAdd(acc + ch, s);
        atomicAdd(acc + 64 + ch, q);
    }
}

__global__ void bn_final(const float* __restrict__ acc, const float* __restrict__ gamma,
                         const float* __restrict__ beta,
                         float* __restrict__ scale, float* __restrict__ shift) {
    int ch = threadIdx.x;
    if (ch >= 64) return;
    const float invN = 1.0f / (float)NN;
    float mu = acc[ch] * invN;
    float var = acc[64 + ch] * invN - mu * mu;
    float sc = gamma[ch] * rsqrtf(var + 1e-5f);
    scale[ch] = sc;
    shift[ch] = beta[ch] - mu * sc;
}

// ---------------- launcher ----------------
extern "C" void kernel_launch(void* const* d_in, const int* in_sizes, int n_in,
                              void* d_out, int out_size) {
    const float* x      = (const float*)d_in[0];
    const int*   ei     = (const int*)d_in[1];
    const int*   etype  = (const int*)d_in[2];
    const float* w1     = (const float*)d_in[3];
    const float* root1  = (const float*)d_in[4];
    const float* b1     = (const float*)d_in[5];
    const float* gamma1 = (const float*)d_in[6];
    const float* beta1  = (const float*)d_in[7];
    const float* w2     = (const float*)d_in[8];
    const float* root2  = (const float*)d_in[9];
    const float* b2     = (const float*)d_in[10];
    float* out = (float*)d_out;

    __half *y;
    float *h, *acc, *scale, *shift;
    unsigned *cnt, *off, *woff, *bsum;
    int *ssrc;
    __nv_bfloat16 *wp1, *wp2;
    cudaGetSymbolAddress((void**)&y, g_y);
    cudaGetSymbolAddress((void**)&h, g_h);
    cudaGetSymbolAddress((void**)&cnt, g_cnt);
    cudaGetSymbolAddress((void**)&off, g_off);
    cudaGetSymbolAddress((void**)&woff, g_woff);
    cudaGetSymbolAddress((void**)&bsum, g_bsum);
    cudaGetSymbolAddress((void**)&ssrc, g_ssrc);
    cudaGetSymbolAddress((void**)&acc, g_acc);
    cudaGetSymbolAddress((void**)&scale, g_scale);
    cudaGetSymbolAddress((void**)&shift, g_shift);
    cudaGetSymbolAddress((void**)&wp1, g_wp1);
    cudaGetSymbolAddress((void**)&wp2, g_wp2);

    cudaFuncSetAttribute(gemm_kernel<false>, cudaFuncAttributeMaxDynamicSharedMemorySize, SMEM_BYTES);
    cudaFuncSetAttribute(gemm_kernel<true>,  cudaFuncAttributeMaxDynamicSharedMemorySize, SMEM_BYTES);

    const int MT = (NN + 63) / 64;             // 1563
    const int NB1 = (NSEG + 2047) / 2048;      // 391

    cudaMemsetAsync(cnt, 0, NSEG * sizeof(unsigned), 0);
    cudaMemsetAsync(acc, 0, 128 * sizeof(float), 0);

    prep_w<<<(576 * KW + 255) / 256, 256>>>(w1, root1, wp1);   // 1
    prep_w<<<(576 * KW + 255) / 256, 256>>>(w2, root2, wp2);   // 2
    hist_kernel<<<(EE + 255) / 256, 256>>>(ei, etype, cnt);    // 3
    gemm_kernel<false><<<MT, 256, SMEM_BYTES>>>(x, wp1, b1, nullptr, nullptr, y, h); // 4 (profiled)
    scan1<<<NB1, 256>>>(cnt, off, bsum);                       // 5
    scan2<<<1, 512>>>(bsum, NB1);                              // 6
    scan3<<<(NSEG + 255) / 256, 256>>>(off, woff, bsum);       // 7
    sort_kernel<<<(EE + 255) / 256, 256>>>(ei, etype, woff, ssrc); // 8
    scatter_kernel<<<(NN + 7) / 8, 256>>>(y, off, ssrc, h);    // 9
    bn_stats<<<1024, 256>>>(h, acc);                           // 10
    bn_final<<<1, 64>>>(acc, gamma1, beta1, scale, shift);     // 11
    gemm_kernel<true><<<MT, 256, SMEM_BYTES>>>(h, wp2, b2, scale, shift, y, out); // 12
    scatter_kernel<<<(NN + 7) / 8, 256>>>(y, off, ssrc, out);  // 13
}